// round 10
// baseline (speedup 1.0000x reference)
#include <cuda_runtime.h>
#include <cuda_fp16.h>
#include <math.h>
#include <stdint.h>

#define EMBED  1024
#define NHEADS 16
#define HDIM   64
#define VOCAB  4096
#define BATCH  2
#define SQL    1024
#define SKVL   2048

// ---------------------------------------------------------------------------
// Scratch (allocation-free __device__ globals)
// ---------------------------------------------------------------------------
__device__ __align__(16) __half g_Qh [BATCH * SQL  * EMBED];
__device__ __align__(16) __half g_Ql [BATCH * SQL  * EMBED];
__device__ __align__(16) __half g_Kh [BATCH * SKVL * EMBED];
__device__ __align__(16) __half g_Kl [BATCH * SKVL * EMBED];
__device__ __align__(16) __half g_Vh [BATCH * SKVL * EMBED];
__device__ __align__(16) __half g_Vl [BATCH * SKVL * EMBED];
__device__ __align__(16) __half g_xh [BATCH * SQL  * EMBED];
__device__ __align__(16) __half g_xl [BATCH * SQL  * EMBED];
__device__ __align__(16) __half g_ch [BATCH * SKVL * EMBED];
__device__ __align__(16) __half g_cl [BATCH * SKVL * EMBED];
__device__ __align__(16) __half g_aoh[BATCH * SQL  * EMBED];
__device__ __align__(16) __half g_aol[BATCH * SQL  * EMBED];
__device__ __align__(16) __half g_WqTh[EMBED * EMBED];
__device__ __align__(16) __half g_WqTl[EMBED * EMBED];
__device__ __align__(16) __half g_WkTh[EMBED * EMBED];
__device__ __align__(16) __half g_WkTl[EMBED * EMBED];
__device__ __align__(16) __half g_WvTh[EMBED * EMBED];
__device__ __align__(16) __half g_WvTl[EMBED * EMBED];
__device__ __align__(16) __half g_WpTh[VOCAB * EMBED];
__device__ __align__(16) __half g_WpTl[VOCAB * EMBED];

// ---------------------------------------------------------------------------
// Helpers
// ---------------------------------------------------------------------------
__device__ __forceinline__ uint32_t smem_u32(const void* p) {
    uint32_t a;
    asm("{ .reg .u64 t; cvta.to.shared.u64 t, %1; cvt.u32.u64 %0, t; }"
        : "=r"(a) : "l"(p));
    return a;
}
__device__ __forceinline__ void cpasync16(uint32_t dst, const void* src) {
    asm volatile("cp.async.cg.shared.global [%0], [%1], 16;"
                 :: "r"(dst), "l"(src) : "memory");
}
#define CP_COMMIT() asm volatile("cp.async.commit_group;" ::: "memory")
#define CP_WAIT(N)  asm volatile("cp.async.wait_group %0;" :: "n"(N) : "memory")

// fp16 inputs, fp32 accumulate (main term)
__device__ __forceinline__ void mma16816(float* c, const uint32_t* a,
                                         uint32_t b0, uint32_t b1) {
    asm volatile(
        "mma.sync.aligned.m16n8k16.row.col.f32.f16.f16.f32 "
        "{%0,%1,%2,%3}, {%4,%5,%6,%7}, {%8,%9}, {%0,%1,%2,%3};"
        : "+f"(c[0]), "+f"(c[1]), "+f"(c[2]), "+f"(c[3])
        : "r"(a[0]), "r"(a[1]), "r"(a[2]), "r"(a[3]), "r"(b0), "r"(b1));
}
// fp16 inputs, fp16 accumulate (correction terms; magnitudes ~2^-11 of main)
__device__ __forceinline__ void mma16816h(uint32_t* c, const uint32_t* a,
                                          uint32_t b0, uint32_t b1) {
    asm volatile(
        "mma.sync.aligned.m16n8k16.row.col.f16.f16.f16.f16 "
        "{%0,%1}, {%2,%3,%4,%5}, {%6,%7}, {%0,%1};"
        : "+r"(c[0]), "+r"(c[1])
        : "r"(a[0]), "r"(a[1]), "r"(a[2]), "r"(a[3]), "r"(b0), "r"(b1));
}
__device__ __forceinline__ void ldsm_x4(uint32_t* r, uint32_t addr) {
    asm volatile("ldmatrix.sync.aligned.m8n8.x4.shared.b16 {%0,%1,%2,%3}, [%4];"
                 : "=r"(r[0]), "=r"(r[1]), "=r"(r[2]), "=r"(r[3]) : "r"(addr));
}
__device__ __forceinline__ void ldsm_x4_t(uint32_t* r, uint32_t addr) {
    asm volatile("ldmatrix.sync.aligned.m8n8.x4.trans.shared.b16 {%0,%1,%2,%3}, [%4];"
                 : "=r"(r[0]), "=r"(r[1]), "=r"(r[2]), "=r"(r[3]) : "r"(addr));
}

__device__ __forceinline__ uint32_t pack2(__half a, __half b) {
    __half2 t = __halves2half2(a, b);
    return *(uint32_t*)&t;
}
__device__ __forceinline__ void split1(float v, __half& h, __half& l) {
    h = __float2half_rn(v);
    l = __float2half_rn(v - __half2float(h));
}
__device__ __forceinline__ void split2(float a, float b, uint32_t& h, uint32_t& l) {
    __half ha = __float2half_rn(a), hb = __float2half_rn(b);
    __half la = __float2half_rn(a - __half2float(ha));
    __half lb = __float2half_rn(b - __half2float(hb));
    h = pack2(ha, hb);
    l = pack2(la, lb);
}
// fold an f16x2-pair correction accumulator into the 4-float main accumulator
__device__ __forceinline__ void fold2(float* c, const uint32_t* k) {
    __half2 x = *(const __half2*)&k[0];
    __half2 y = *(const __half2*)&k[1];
    c[0] += __low2float(x); c[1] += __high2float(x);
    c[2] += __low2float(y); c[3] += __high2float(y);
}

#define SWZ(off) ((uint32_t)(off) ^ ((((uint32_t)(off)) >> 3) & 0x70u))

// ---------------------------------------------------------------------------
// fp32 -> fp16 hi/lo split
// ---------------------------------------------------------------------------
__global__ __launch_bounds__(256) void split_f32(
    const float4* __restrict__ in,
    __half* __restrict__ hi, __half* __restrict__ lo, int n4)
{
    int i = blockIdx.x * 256 + threadIdx.x;
    if (i >= n4) return;
    float4 v = in[i];
    __half h[4], l[4];
    split1(v.x, h[0], l[0]); split1(v.y, h[1], l[1]);
    split1(v.z, h[2], l[2]); split1(v.w, h[3], l[3]);
    *(uint2*)&hi[i * 4] = *(uint2*)h;
    *(uint2*)&lo[i * 4] = *(uint2*)l;
}

// ---------------------------------------------------------------------------
// Weight transpose + split (z selects one of up to 3 weight sets)
// ---------------------------------------------------------------------------
struct TSet { const float* W; __half* Wh; __half* Wl; };
struct TArgs { TSet s[3]; };

__device__ __forceinline__ void transpose_body(
    const float* __restrict__ W, __half* __restrict__ WhT,
    __half* __restrict__ WlT, int K, int N)
{
    __shared__ float t[32][33];
    int n  = blockIdx.x * 32 + threadIdx.x;
    int k0 = blockIdx.y * 32;
    for (int j = threadIdx.y; j < 32; j += 8)
        t[j][threadIdx.x] = W[(size_t)(k0 + j) * N + n];
    __syncthreads();
    int k  = blockIdx.y * 32 + threadIdx.x;
    int n0 = blockIdx.x * 32;
    for (int j = threadIdx.y; j < 32; j += 8) {
        float v = t[threadIdx.x][j];
        __half h, l;
        split1(v, h, l);
        WhT[(size_t)(n0 + j) * K + k] = h;
        WlT[(size_t)(n0 + j) * K + k] = l;
    }
}
__global__ void transpose_split3(TArgs a, int K, int N) {
    const TSet& s = a.s[blockIdx.z];
    transpose_body(s.W, s.Wh, s.Wl, K, N);
}
__global__ void transpose_split(const float* __restrict__ W,
                                __half* __restrict__ WhT,
                                __half* __restrict__ WlT, int K, int N) {
    transpose_body(W, WhT, WlT, K, N);
}

// ---------------------------------------------------------------------------
// fp16x3 GEMM core: C = (Ah+Al) @ ((Bh+Bl))^T + bias, dropping Al*Bl.
// Main term -> f32-accum HMMA; both cross terms -> f16-accum HMMA into a
// shared f16x2 accumulator, folded into the f32 acc once per k-tile.
// ---------------------------------------------------------------------------
#define PITCH_B   80
#define TILE_B    (128 * PITCH_B)
#define OFF_AHI   0
#define OFF_ALO   (TILE_B)
#define OFF_BHI   (2 * TILE_B)
#define OFF_BLO   (3 * TILE_B)
#define BUF_B     (4 * TILE_B)
#define GEMM_SMEM (2 * BUF_B)

template<bool SPLIT>
__device__ __forceinline__ void gemm_core(
    const __half* __restrict__ Ah, const __half* __restrict__ Al,
    const __half* __restrict__ Bh, const __half* __restrict__ Bl,
    const float* __restrict__ bias, float* __restrict__ C,
    __half* __restrict__ Ch, __half* __restrict__ Cl,
    int N, int K, char* smem)
{
    const uint32_t sbase = smem_u32(smem);

    const int tid  = threadIdx.x;
    const int wid  = tid >> 5;
    const int lane = tid & 31;
    const int wm   = wid & 1;
    const int wn   = wid >> 1;
    const int lr   = lane >> 2;
    const int lc   = lane & 3;

    const int m0 = blockIdx.y * 128;
    const int n0 = blockIdx.x * 128;

    const int lrow0 = tid >> 2;
    const int lcc0  = tid & 3;

    const size_t aBase = (size_t)m0 * K;
    const size_t bBase = (size_t)n0 * K;

    auto load_tile = [&](int buf, int kt) {
        uint32_t sb = sbase + buf * BUF_B;
        const size_t gk = (size_t)kt * 32;
#pragma unroll
        for (int j = 0; j < 2; ++j) {
            int row = lrow0 + j * 64;
            uint32_t soff = (uint32_t)(row * PITCH_B + lcc0 * 16);
            size_t   goff = aBase + (size_t)row * K + gk + lcc0 * 8;
            cpasync16(sb + OFF_AHI + soff, Ah + goff);
            cpasync16(sb + OFF_ALO + soff, Al + goff);
            size_t   goffb = bBase + (size_t)row * K + gk + lcc0 * 8;
            cpasync16(sb + OFF_BHI + soff, Bh + goffb);
            cpasync16(sb + OFF_BLO + soff, Bl + goffb);
        }
        CP_COMMIT();
    };

    float acc[4][4][4];
#pragma unroll
    for (int i = 0; i < 4; ++i)
#pragma unroll
        for (int j = 0; j < 4; ++j)
#pragma unroll
            for (int r = 0; r < 4; ++r) acc[i][j][r] = 0.f;

    const uint32_t aOff = (uint32_t)((wm * 64 + (lane & 15)) * PITCH_B
                                     + (lane >> 4) * 16);
    const uint32_t bOff = (uint32_t)((wn * 32 + (lane & 15)) * PITCH_B
                                     + (lane >> 4) * 16);

    load_tile(0, 0);

    const int nk = K >> 5;
    for (int kt = 0; kt < nk; ++kt) {
        const int cur = kt & 1;
        if (kt + 1 < nk) { load_tile(cur ^ 1, kt + 1); CP_WAIT(1); }
        else             { CP_WAIT(0); }
        __syncthreads();

        const uint32_t sA_h = sbase + cur * BUF_B + OFF_AHI;
        const uint32_t sA_l = sbase + cur * BUF_B + OFF_ALO;
        const uint32_t sB_h = sbase + cur * BUF_B + OFF_BHI;
        const uint32_t sB_l = sbase + cur * BUF_B + OFF_BLO;

        uint32_t corr[4][4][2];
#pragma unroll
        for (int i = 0; i < 4; ++i)
#pragma unroll
            for (int j = 0; j < 4; ++j) { corr[i][j][0] = 0u; corr[i][j][1] = 0u; }

#pragma unroll
        for (int ks = 0; ks < 2; ++ks) {
            const uint32_t ko = (uint32_t)(ks * 32);

            uint32_t ah[4][4];
#pragma unroll
            for (int mi = 0; mi < 4; ++mi)
                ldsm_x4(ah[mi], sA_h + aOff + mi * (16 * PITCH_B) + ko);
            uint32_t bh[2][4];
#pragma unroll
            for (int g = 0; g < 2; ++g)
                ldsm_x4(bh[g], sB_h + bOff + g * (16 * PITCH_B) + ko);

            // main term: f32 accumulate
#pragma unroll
            for (int mi = 0; mi < 4; ++mi)
#pragma unroll
                for (int ni = 0; ni < 4; ++ni)
                    mma16816(acc[mi][ni], ah[mi],
                             bh[ni >> 1][ni & 1], bh[ni >> 1][(ni & 1) + 2]);

            uint32_t bl[2][4];
#pragma unroll
            for (int g = 0; g < 2; ++g)
                ldsm_x4(bl[g], sB_l + bOff + g * (16 * PITCH_B) + ko);
            uint32_t al[4][4];
#pragma unroll
            for (int mi = 0; mi < 4; ++mi)
                ldsm_x4(al[mi], sA_l + aOff + mi * (16 * PITCH_B) + ko);

            // cross terms: f16 accumulate (shared accumulator)
#pragma unroll
            for (int mi = 0; mi < 4; ++mi)
#pragma unroll
                for (int ni = 0; ni < 4; ++ni) {
                    mma16816h(corr[mi][ni], ah[mi],
                              bl[ni >> 1][ni & 1], bl[ni >> 1][(ni & 1) + 2]);
                    mma16816h(corr[mi][ni], al[mi],
                              bh[ni >> 1][ni & 1], bh[ni >> 1][(ni & 1) + 2]);
                }
        }
#pragma unroll
        for (int mi = 0; mi < 4; ++mi)
#pragma unroll
            for (int ni = 0; ni < 4; ++ni)
                fold2(acc[mi][ni], corr[mi][ni]);
        __syncthreads();
    }

#pragma unroll
    for (int mi = 0; mi < 4; ++mi) {
        int r = m0 + wm * 64 + mi * 16 + lr;
#pragma unroll
        for (int ni = 0; ni < 4; ++ni) {
            int c = n0 + wn * 32 + ni * 8 + lc * 2;
            float b0 = __ldg(bias + c), b1 = __ldg(bias + c + 1);
            float v00 = acc[mi][ni][0] + b0, v01 = acc[mi][ni][1] + b1;
            float v10 = acc[mi][ni][2] + b0, v11 = acc[mi][ni][3] + b1;
            if (SPLIT) {
                uint32_t h, l;
                split2(v00, v01, h, l);
                *(uint32_t*)&Ch[(size_t)r * N + c] = h;
                *(uint32_t*)&Cl[(size_t)r * N + c] = l;
                split2(v10, v11, h, l);
                *(uint32_t*)&Ch[(size_t)(r + 8) * N + c] = h;
                *(uint32_t*)&Cl[(size_t)(r + 8) * N + c] = l;
            } else {
                *(float2*)&C[(size_t)r * N + c]       = make_float2(v00, v01);
                *(float2*)&C[(size_t)(r + 8) * N + c] = make_float2(v10, v11);
            }
        }
    }
}

__global__ __launch_bounds__(256) void gemm_out(
    const __half* __restrict__ Ah, const __half* __restrict__ Al,
    const __half* __restrict__ Bh, const __half* __restrict__ Bl,
    const float* __restrict__ bias, float* __restrict__ C, int N, int K)
{
    extern __shared__ char smem[];
    gemm_core<false>(Ah, Al, Bh, Bl, bias, C, nullptr, nullptr, N, K, smem);
}

struct GSet {
    const __half *Ah, *Al, *Bh, *Bl;
    const float* bias;
    __half *Ch, *Cl;
};
struct QKVArgs { GSet s[3]; };

__global__ __launch_bounds__(256) void gemm_qkv(QKVArgs a)
{
    extern __shared__ char smem[];
    if (blockIdx.z == 0 && blockIdx.y >= (BATCH * SQL) / 128) return;
    const GSet& s = a.s[blockIdx.z];
    gemm_core<true>(s.Ah, s.Al, s.Bh, s.Bl, s.bias, nullptr, s.Ch, s.Cl,
                    EMBED, EMBED, smem);
}

// ---------------------------------------------------------------------------
// Tensor-core flash attention (fp16x3; cross terms on f16-accum HMMA)
// ---------------------------------------------------------------------------
#define FSM_QH   0
#define FSM_QL   16384
#define FSM_ST   32768
#define ST_KH    0
#define ST_KL    8192
#define ST_VH    16384
#define ST_VL    24576
#define ST_SZ    32768
#define FLASH_SMEM (FSM_ST + 2 * ST_SZ)   // 98304 B

__global__ __launch_bounds__(256) void flash_mma()
{
    extern __shared__ char sm[];
    const uint32_t sb = smem_u32(sm);

    const int tid  = threadIdx.x;
    const int wid  = tid >> 5;
    const int lane = tid & 31;
    const int b    = blockIdx.y >> 4;
    const int h    = blockIdx.y & 15;
    const int q0   = blockIdx.x * 128;

    {
        const size_t qtok = (size_t)(b * SQL + q0);
#pragma unroll
        for (int i = 0; i < 4; ++i) {
            int idx = i * 256 + tid;
            int r = idx >> 3, cc = idx & 7;
            uint32_t off = SWZ(r * 128 + cc * 16);
            size_t g = (qtok + r) * EMBED + h * 64 + cc * 8;
            cpasync16(sb + FSM_QH + off, g_Qh + g);
            cpasync16(sb + FSM_QL + off, g_Ql + g);
        }
    }
    auto load_kv = [&](int buf, int kb) {
        uint32_t st = sb + FSM_ST + buf * ST_SZ;
        const size_t tok = (size_t)(b * SKVL + kb * 64);
#pragma unroll
        for (int i = 0; i < 2; ++i) {
            int idx = i * 256 + tid;
            int r = idx >> 3, cc = idx & 7;
            uint32_t off = SWZ(r * 128 + cc * 16);
            size_t g = (tok + r) * EMBED + h * 64 + cc * 8;
            cpasync16(st + ST_KH + off, g_Kh + g);
            cpasync16(st + ST_KL + off, g_Kl + g);
            cpasync16(st + ST_VH + off, g_Vh + g);
            cpasync16(st + ST_VL + off, g_Vl + g);
        }
    };
    load_kv(0, 0);
    CP_COMMIT();

    float m_[2] = {-1e30f, -1e30f};
    float l_[2] = {0.f, 0.f};
    float o[8][4];
#pragma unroll
    for (int i = 0; i < 8; ++i)
#pragma unroll
        for (int j = 0; j < 4; ++j) o[i][j] = 0.f;

    const int lrow = lane & 15;
    const int lchk = lane >> 4;
    const float scale = 0.125f;

    const int NCH = SKVL / 64;
    for (int ch = 0; ch < NCH; ++ch) {
        const int cur = ch & 1;
        if (ch + 1 < NCH) { load_kv(cur ^ 1, ch + 1); CP_COMMIT(); CP_WAIT(1); }
        else              { CP_WAIT(0); }
        __syncthreads();

        const uint32_t st = sb + FSM_ST + cur * ST_SZ;

        float s[8][4];
        uint32_t scorr[8][2];
#pragma unroll
        for (int i = 0; i < 8; ++i) {
            s[i][0] = s[i][1] = s[i][2] = s[i][3] = 0.f;
            scorr[i][0] = 0u; scorr[i][1] = 0u;
        }

#pragma unroll
        for (int kk = 0; kk < 4; ++kk) {
            uint32_t qoff = SWZ((wid * 16 + lrow) * 128 + (kk * 2 + lchk) * 16);
            uint32_t qh[4], ql[4];
            ldsm_x4(qh, sb + FSM_QH + qoff);
            ldsm_x4(ql, sb + FSM_QL + qoff);
#pragma unroll
            for (int cg = 0; cg < 4; ++cg) {
                uint32_t koff = SWZ((cg * 16 + lrow) * 128 + (kk * 2 + lchk) * 16);
                uint32_t kh[4], kl[4];
                ldsm_x4(kh, st + ST_KH + koff);
                ldsm_x4(kl, st + ST_KL + koff);
                mma16816(s[2 * cg],     qh, kh[0], kh[2]);
                mma16816(s[2 * cg + 1], qh, kh[1], kh[3]);
                mma16816h(scorr[2 * cg],     qh, kl[0], kl[2]);
                mma16816h(scorr[2 * cg],     ql, kh[0], kh[2]);
                mma16816h(scorr[2 * cg + 1], qh, kl[1], kl[3]);
                mma16816h(scorr[2 * cg + 1], ql, kh[1], kh[3]);
            }
        }
#pragma unroll
        for (int ni = 0; ni < 8; ++ni) fold2(s[ni], scorr[ni]);

        float rm0 = -1e30f, rm1 = -1e30f;
#pragma unroll
        for (int ni = 0; ni < 8; ++ni) {
            rm0 = fmaxf(rm0, fmaxf(s[ni][0], s[ni][1]));
            rm1 = fmaxf(rm1, fmaxf(s[ni][2], s[ni][3]));
        }
        rm0 = fmaxf(rm0, __shfl_xor_sync(0xffffffffu, rm0, 1));
        rm0 = fmaxf(rm0, __shfl_xor_sync(0xffffffffu, rm0, 2));
        rm1 = fmaxf(rm1, __shfl_xor_sync(0xffffffffu, rm1, 1));
        rm1 = fmaxf(rm1, __shfl_xor_sync(0xffffffffu, rm1, 2));

        float mn0 = fmaxf(m_[0], rm0 * scale);
        float mn1 = fmaxf(m_[1], rm1 * scale);
        float a0 = __expf(m_[0] - mn0);
        float a1 = __expf(m_[1] - mn1);
        m_[0] = mn0; m_[1] = mn1;
#pragma unroll
        for (int nd = 0; nd < 8; ++nd) {
            o[nd][0] *= a0; o[nd][1] *= a0;
            o[nd][2] *= a1; o[nd][3] *= a1;
        }
        float rs0 = 0.f, rs1 = 0.f;
#pragma unroll
        for (int ni = 0; ni < 8; ++ni) {
            s[ni][0] = __expf(fmaf(s[ni][0], scale, -mn0));
            s[ni][1] = __expf(fmaf(s[ni][1], scale, -mn0));
            s[ni][2] = __expf(fmaf(s[ni][2], scale, -mn1));
            s[ni][3] = __expf(fmaf(s[ni][3], scale, -mn1));
            rs0 += s[ni][0] + s[ni][1];
            rs1 += s[ni][2] + s[ni][3];
        }
        rs0 += __shfl_xor_sync(0xffffffffu, rs0, 1);
        rs0 += __shfl_xor_sync(0xffffffffu, rs0, 2);
        rs1 += __shfl_xor_sync(0xffffffffu, rs1, 1);
        rs1 += __shfl_xor_sync(0xffffffffu, rs1, 2);
        l_[0] = l_[0] * a0 + rs0;
        l_[1] = l_[1] * a1 + rs1;

        uint32_t ocorr[8][2];
#pragma unroll
        for (int i = 0; i < 8; ++i) { ocorr[i][0] = 0u; ocorr[i][1] = 0u; }

#pragma unroll
        for (int kc = 0; kc < 4; ++kc) {
            uint32_t ph[4], pl[4];
            split2(s[2 * kc][0],     s[2 * kc][1],     ph[0], pl[0]);
            split2(s[2 * kc][2],     s[2 * kc][3],     ph[1], pl[1]);
            split2(s[2 * kc + 1][0], s[2 * kc + 1][1], ph[2], pl[2]);
            split2(s[2 * kc + 1][2], s[2 * kc + 1][3], ph[3], pl[3]);
#pragma unroll
            for (int g = 0; g < 4; ++g) {
                uint32_t voff = SWZ((kc * 16 + lrow) * 128 + (g * 2 + lchk) * 16);
                uint32_t vh[4], vl[4];
                ldsm_x4_t(vh, st + ST_VH + voff);
                ldsm_x4_t(vl, st + ST_VL + voff);
                mma16816(o[2 * g],     ph, vh[0], vh[1]);
                mma16816(o[2 * g + 1], ph, vh[2], vh[3]);
                mma16816h(ocorr[2 * g],     ph, vl[0], vl[1]);
                mma16816h(ocorr[2 * g],     pl, vh[0], vh[1]);
                mma16816h(ocorr[2 * g + 1], ph, vl[2], vl[3]);
                mma16816h(ocorr[2 * g + 1], pl, vh[2], vh[3]);
            }
        }
#pragma unroll
        for (int nd = 0; nd < 8; ++nd) fold2(o[nd], ocorr[nd]);
        __syncthreads();
    }

    const float inv0 = 1.f / l_[0];
    const float inv1 = 1.f / l_[1];
    const int r0 = q0 + wid * 16 + (lane >> 2);
    const int cb = h * 64 + (lane & 3) * 2;
    const size_t tok = (size_t)b * SQL;
#pragma unroll
    for (int nd = 0; nd < 8; ++nd) {
        int c = cb + nd * 8;
        uint32_t hh, ll;
        split2(o[nd][0] * inv0, o[nd][1] * inv0, hh, ll);
        *(uint32_t*)&g_aoh[(tok + r0) * EMBED + c] = hh;
        *(uint32_t*)&g_aol[(tok + r0) * EMBED + c] = ll;
        split2(o[nd][2] * inv1, o[nd][3] * inv1, hh, ll);
        *(uint32_t*)&g_aoh[(tok + r0 + 8) * EMBED + c] = hh;
        *(uint32_t*)&g_aol[(tok + r0 + 8) * EMBED + c] = ll;
    }
}

// ---------------------------------------------------------------------------
// Launch
// ---------------------------------------------------------------------------
extern "C" void kernel_launch(void* const* d_in, const int* in_sizes, int n_in,
                              void* d_out, int out_size)
{
    const float* x   = (const float*)d_in[0];
    const float* ctx = (const float*)d_in[1];
    const float* Wq  = (const float*)d_in[2];
    const float* bq  = (const float*)d_in[3];
    const float* Wk  = (const float*)d_in[4];
    const float* bk  = (const float*)d_in[5];
    const float* Wv  = (const float*)d_in[6];
    const float* bv  = (const float*)d_in[7];
    const float* Wp  = (const float*)d_in[8];
    const float* bp  = (const float*)d_in[9];
    float* out = (float*)d_out;

    __half *Qh, *Ql, *Kh, *Kl, *Vh, *Vl, *xh, *xl, *ch_, *cl_, *aoh, *aol;
    __half *WqTh, *WqTl, *WkTh, *WkTl, *WvTh, *WvTl, *WpTh, *WpTl;
    cudaGetSymbolAddress((void**)&Qh,  g_Qh);
    cudaGetSymbolAddress((void**)&Ql,  g_Ql);
    cudaGetSymbolAddress((void**)&Kh,  g_Kh);
    cudaGetSymbolAddress((void**)&Kl,  g_Kl);
    cudaGetSymbolAddress((void**)&Vh,  g_Vh);
    cudaGetSymbolAddress((void**)&Vl,  g_Vl);
    cudaGetSymbolAddress((void**)&xh,  g_xh);
    cudaGetSymbolAddress((void**)&xl,  g_xl);
    cudaGetSymbolAddress((void**)&ch_, g_ch);
    cudaGetSymbolAddress((void**)&cl_, g_cl);
    cudaGetSymbolAddress((void**)&aoh, g_aoh);
    cudaGetSymbolAddress((void**)&aol, g_aol);
    cudaGetSymbolAddress((void**)&WqTh, g_WqTh);
    cudaGetSymbolAddress((void**)&WqTl, g_WqTl);
    cudaGetSymbolAddress((void**)&WkTh, g_WkTh);
    cudaGetSymbolAddress((void**)&WkTl, g_WkTl);
    cudaGetSymbolAddress((void**)&WvTh, g_WvTh);
    cudaGetSymbolAddress((void**)&WvTl, g_WvTl);
    cudaGetSymbolAddress((void**)&WpTh, g_WpTh);
    cudaGetSymbolAddress((void**)&WpTl, g_WpTl);

    cudaFuncSetAttribute(gemm_qkv,
                         cudaFuncAttributeMaxDynamicSharedMemorySize, GEMM_SMEM);
    cudaFuncSetAttribute(gemm_out,
                         cudaFuncAttributeMaxDynamicSharedMemorySize, GEMM_SMEM);
    cudaFuncSetAttribute(flash_mma,
                         cudaFuncAttributeMaxDynamicSharedMemorySize, FLASH_SMEM);

    const int NX = BATCH * SQL  * EMBED;
    const int NC = BATCH * SKVL * EMBED;

    split_f32<<<(NX / 4 + 255) / 256, 256>>>((const float4*)x,   xh,  xl,  NX / 4);
    split_f32<<<(NC / 4 + 255) / 256, 256>>>((const float4*)ctx, ch_, cl_, NC / 4);

    TArgs ta;
    ta.s[0] = {Wq, WqTh, WqTl};
    ta.s[1] = {Wk, WkTh, WkTl};
    ta.s[2] = {Wv, WvTh, WvTl};
    transpose_split3<<<dim3(EMBED / 32, EMBED / 32, 3), dim3(32, 8)>>>(ta, EMBED, EMBED);
    transpose_split<<<dim3(VOCAB / 32, EMBED / 32), dim3(32, 8)>>>(Wp, WpTh, WpTl, EMBED, VOCAB);

    QKVArgs qa;
    qa.s[0] = {xh,  xl,  WqTh, WqTl, bq, Qh, Ql};
    qa.s[1] = {ch_, cl_, WkTh, WkTl, bk, Kh, Kl};
    qa.s[2] = {ch_, cl_, WvTh, WvTl, bv, Vh, Vl};
    gemm_qkv<<<dim3(EMBED / 128, (BATCH * SKVL) / 128, 3), 256, GEMM_SMEM>>>(qa);

    flash_mma<<<dim3(SQL / 128, BATCH * NHEADS), 256, FLASH_SMEM>>>();

    gemm_out<<<dim3(VOCAB / 128, (BATCH * SQL) / 128), 256, GEMM_SMEM>>>(
        aoh, aol, WpTh, WpTl, bp, out, VOCAB, EMBED);
}